// round 13
// baseline (speedup 1.0000x reference)
#include <cuda_runtime.h>
#include <cuda_bf16.h>
#include <cstdint>
#include <math.h>

#define B_SZ 8192
#define D_SZ 256
#define INV_T (1.0f / 0.07f)
#define KC (1.4426950408889634f / 0.07f)   // log2(e)/T
#define NJOB 4096                           // 64 rowtiles x 64 chunks

// ---------------- scratch (no allocations allowed) ----------------
__device__ __align__(16) __nv_bfloat16 g_q[B_SZ * D_SZ];   // 4 MB
__device__ __align__(16) __nv_bfloat16 g_t[B_SZ * D_SZ];   // 4 MB
__device__ float g_pos[B_SZ];
__device__ float g_part[NJOB * 512];        // per job: 4 col-quarters x 128 rows (8 MB)
__device__ double g_bred[32];
__device__ unsigned int g_cnt;              // jobs-done counter (gemm CTAs)
__device__ unsigned int g_cnt2;             // reduce-blocks counter

// ---------------- kernel 1: normalize (1 row/warp) ----------------
__global__ __launch_bounds__(256) void norm_kernel(const float* __restrict__ h,
                                                   const float* __restrict__ r,
                                                   const float* __restrict__ t) {
    if (blockIdx.x == 0 && threadIdx.x == 0) { g_cnt = 0; g_cnt2 = 0; }

    int wid = threadIdx.x >> 5;
    int lane = threadIdx.x & 31;
    int row = blockIdx.x * 8 + wid;

    const float4* h4 = (const float4*)h;
    const float4* r4 = (const float4*)r;
    const float4* t4 = (const float4*)t;
    int base = row * 64;

    float4 ha = h4[base + lane];
    float4 hb = h4[base + 32 + lane];
    float4 ra = r4[base + lane];
    float4 rb = r4[base + 32 + lane];
    float4 ta = t4[base + lane];
    float4 tb = t4[base + 32 + lane];

    float4 va = make_float4(ha.x + ra.x, ha.y + ra.y, ha.z + ra.z, ha.w + ra.w);
    float4 vb = make_float4(hb.x + rb.x, hb.y + rb.y, hb.z + rb.z, hb.w + rb.w);

    float ss = va.x * va.x + va.y * va.y + va.z * va.z + va.w * va.w +
               vb.x * vb.x + vb.y * vb.y + vb.z * vb.z + vb.w * vb.w;
    float ts = ta.x * ta.x + ta.y * ta.y + ta.z * ta.z + ta.w * ta.w +
               tb.x * tb.x + tb.y * tb.y + tb.z * tb.z + tb.w * tb.w;
#pragma unroll
    for (int o = 16; o > 0; o >>= 1) {
        ss += __shfl_xor_sync(0xffffffffu, ss, o);
        ts += __shfl_xor_sync(0xffffffffu, ts, o);
    }
    float qinv = rsqrtf(fmaxf(ss, 1e-24f));
    float tinv = rsqrtf(fmaxf(ts, 1e-24f));

    float qa0 = va.x * qinv, qa1 = va.y * qinv, qa2 = va.z * qinv, qa3 = va.w * qinv;
    float qb0 = vb.x * qinv, qb1 = vb.y * qinv, qb2 = vb.z * qinv, qb3 = vb.w * qinv;
    float ta0 = ta.x * tinv, ta1 = ta.y * tinv, ta2 = ta.z * tinv, ta3 = ta.w * tinv;
    float tb0 = tb.x * tinv, tb1 = tb.y * tinv, tb2 = tb.z * tinv, tb3 = tb.w * tinv;

    __nv_bfloat162* q2 = (__nv_bfloat162*)(g_q + row * D_SZ);
    __nv_bfloat162* t2 = (__nv_bfloat162*)(g_t + row * D_SZ);
    int c2 = lane * 2;
    q2[c2]      = __floats2bfloat162_rn(qa0, qa1);
    q2[c2 + 1]  = __floats2bfloat162_rn(qa2, qa3);
    q2[c2 + 64] = __floats2bfloat162_rn(qb0, qb1);
    q2[c2 + 65] = __floats2bfloat162_rn(qb2, qb3);
    t2[c2]      = __floats2bfloat162_rn(ta0, ta1);
    t2[c2 + 1]  = __floats2bfloat162_rn(ta2, ta3);
    t2[c2 + 64] = __floats2bfloat162_rn(tb0, tb1);
    t2[c2 + 65] = __floats2bfloat162_rn(tb2, tb3);

    float p = qa0 * ta0 + qa1 * ta1 + qa2 * ta2 + qa3 * ta3 +
              qb0 * tb0 + qb1 * tb1 + qb2 * tb2 + qb3 * tb3;
#pragma unroll
    for (int o = 16; o > 0; o >>= 1) p += __shfl_xor_sync(0xffffffffu, p, o);
    if (lane == 0) g_pos[row] = p * INV_T;
}

// ---------------- kernel 2: persistent HMMA GEMM (512 thr) + exp-sum + reduce tail ----------------
#define NT 512
#define SQ 264                               // bf16 elems per smem row (+pad)
#define TBYTES (128 * SQ * 2)                // 67584 B per tile
#define QOFF 0
#define T0OFF TBYTES
#define T1OFF (2 * TBYTES)
#define SMEM_TOTAL (3 * TBYTES)

__device__ __forceinline__ void cp16(uint32_t dst, const void* src) {
    asm volatile("cp.async.cg.shared.global [%0], [%1], 16;\n" :: "r"(dst), "l"(src));
}
__device__ __forceinline__ void cp_commit() {
    asm volatile("cp.async.commit_group;\n" ::: "memory");
}
template <int N>
__device__ __forceinline__ void cp_wait() {
    asm volatile("cp.async.wait_group %0;\n" :: "n"(N) : "memory");
}

__device__ __forceinline__ void mma_bf16(float c[4], const uint32_t a[4], const uint32_t* b) {
    asm volatile(
        "mma.sync.aligned.m16n8k16.row.col.f32.bf16.bf16.f32 "
        "{%0,%1,%2,%3}, {%4,%5,%6,%7}, {%8,%9}, {%0,%1,%2,%3};\n"
        : "+f"(c[0]), "+f"(c[1]), "+f"(c[2]), "+f"(c[3])
        : "r"(a[0]), "r"(a[1]), "r"(a[2]), "r"(a[3]), "r"(b[0]), "r"(b[1]));
}

__global__ __launch_bounds__(NT, 1) void gemm_lse_kernel(float* __restrict__ out) {
    extern __shared__ char smem[];
    const uint32_t sbase = (uint32_t)__cvta_generic_to_shared(smem);

    const int tid = threadIdx.x;
    const int wid = tid >> 5;
    const int lane = tid & 31;
    const int c = blockIdx.x;
    const int G = gridDim.x;

    const int j0 = (c * NJOB) / G;
    const int j1 = ((c + 1) * NJOB) / G;
    const int nj = j1 - j0;

    int cur_rt = j0 >> 6;

#define LOADQ(rt)                                                              \
    do {                                                                       \
        const __nv_bfloat16* qsrc = g_q + (size_t)((rt) * 128) * D_SZ;         \
        for (int i = tid; i < 128 * 32; i += NT) {                             \
            int rr = i >> 5;                                                   \
            int c8 = (i & 31) * 8;                                             \
            cp16(sbase + QOFF + (rr * SQ + c8) * 2, qsrc + rr * D_SZ + c8);    \
        }                                                                      \
    } while (0)
#define LOADT(off, ch)                                                         \
    do {                                                                       \
        const __nv_bfloat16* tsrc = g_t + (size_t)((ch) * 128) * D_SZ;         \
        for (int i = tid; i < 128 * 32; i += NT) {                             \
            int rr = i >> 5;                                                   \
            int c8 = (i & 31) * 8;                                             \
            cp16(sbase + (off) + (rr * SQ + c8) * 2, tsrc + rr * D_SZ + c8);   \
        }                                                                      \
    } while (0)

    // prologue: group0 = q + t[j0]; group1 = t[j0+1] (possibly empty)
    LOADQ(cur_rt);
    LOADT(T0OFF, j0 & 63);
    cp_commit();
    if (nj > 1) LOADT(T1OFF, (j0 + 1) & 63);
    cp_commit();

    // warp tile: 32 rows x 32 cols; 16 warps as 4 (rows) x 4 (cols)
    const int wr = (wid >> 2) * 32;
    const int wc = (wid & 3) * 32;

    uint32_t aAddr[2];
#pragma unroll
    for (int mt = 0; mt < 2; mt++) {
        int rrow = wr + mt * 16 + (lane & 15);
        aAddr[mt] = sbase + QOFF + (uint32_t)(rrow * SQ + (lane >> 4) * 8) * 2;
    }
    // B: 32 cols = 4 n8 frags; one ldmatrix.x4 covers 2 frags x 2 k-halves
    uint32_t bAddr[2][2];
#pragma unroll
    for (int p = 0; p < 2; p++) {
        int nt = 2 * p + (lane >> 4);
        int khalf = (lane >> 3) & 1;
        int rrow = wc + nt * 8 + (lane & 7);
        uint32_t off = (uint32_t)(rrow * SQ + khalf * 8) * 2;
        bAddr[0][p] = sbase + T0OFF + off;
        bAddr[1][p] = sbase + T1OFF + off;
    }

    for (int i = 0; i < nj; i++) {
        const int ji = j0 + i;
        const int rt = ji >> 6;
        const int cb = i & 1;

        if (rt != cur_rt) {
            LOADQ(rt);
            cp_commit();
            cp_wait<0>();
            cur_rt = rt;
        } else if (i >= nj - 2) {
            cp_wait<0>();
        } else {
            cp_wait<1>();
        }
        __syncthreads();

        float acc[2][4][4];
#pragma unroll
        for (int mt = 0; mt < 2; mt++)
#pragma unroll
            for (int nt = 0; nt < 4; nt++)
#pragma unroll
                for (int k = 0; k < 4; k++) acc[mt][nt][k] = 0.0f;

#pragma unroll
        for (int ks = 0; ks < 16; ks++) {
            uint32_t a[2][4];
            uint32_t b[4][2];
#pragma unroll
            for (int mt = 0; mt < 2; mt++) {
                asm volatile(
                    "ldmatrix.sync.aligned.m8n8.x4.shared.b16 {%0,%1,%2,%3}, [%4];\n"
                    : "=r"(a[mt][0]), "=r"(a[mt][1]), "=r"(a[mt][2]), "=r"(a[mt][3])
                    : "r"(aAddr[mt] + ks * 32));
            }
#pragma unroll
            for (int p = 0; p < 2; p++) {
                asm volatile(
                    "ldmatrix.sync.aligned.m8n8.x4.shared.b16 {%0,%1,%2,%3}, [%4];\n"
                    : "=r"(b[2 * p][0]), "=r"(b[2 * p][1]),
                      "=r"(b[2 * p + 1][0]), "=r"(b[2 * p + 1][1])
                    : "r"(bAddr[cb][p] + ks * 32));
            }
#pragma unroll
            for (int mt = 0; mt < 2; mt++)
#pragma unroll
                for (int nt = 0; nt < 4; nt++) mma_bf16(acc[mt][nt], a[mt], b[nt]);
        }

        // fused epilogue: exp2(acc*KC) -> per-thread row partials -> global
        float s[4];
#pragma unroll
        for (int mt = 0; mt < 2; mt++) {
            float s0 = 0.f, s1 = 0.f;
#pragma unroll
            for (int nt = 0; nt < 4; nt++) {
                s0 += exp2f(acc[mt][nt][0] * KC) + exp2f(acc[mt][nt][1] * KC);
                s1 += exp2f(acc[mt][nt][2] * KC) + exp2f(acc[mt][nt][3] * KC);
            }
            s[mt * 2] = s0;
            s[mt * 2 + 1] = s1;
        }
#pragma unroll
        for (int k = 0; k < 4; k++) {
            float v = s[k];
            v += __shfl_xor_sync(0xffffffffu, v, 1);
            v += __shfl_xor_sync(0xffffffffu, v, 2);
            s[k] = v;
        }
        if ((lane & 3) == 0) {
            int g = lane >> 2;
            float* dst = g_part + (size_t)ji * 512 + (wid & 3) * 128 + wr + g;
            dst[0] = s[0];
            dst[8] = s[1];
            dst[16] = s[2];
            dst[24] = s[3];
        }

        __syncthreads();
        if (i + 2 < nj) LOADT(cb ? T1OFF : T0OFF, (ji + 2) & 63);
        cp_commit();
    }
#undef LOADQ
#undef LOADT

    // ---------- tail: announce done; CTAs 0..31 wait for all, then reduce ----------
    __threadfence();
    __syncthreads();
    if (tid == 0) atomicAdd(&g_cnt, 1u);

    if (c < 32 && tid < 256) {
        if (tid == 0) {
            while (*((volatile unsigned int*)&g_cnt) < (unsigned)G) { __nanosleep(64); }
        }
        asm volatile("bar.sync 1, 256;" ::: "memory");
        __threadfence();  // acquire: see all g_part writes

        double* red = (double*)smem;
        int* flag = (int*)(smem + 2048);
        int row = c * 256 + tid;
        int rt2 = row >> 7, rr2 = row & 127;
        const float* base = g_part + (size_t)(rt2 * 64) * 512 + rr2;
        float sum = 0.f;
#pragma unroll 8
        for (int ch = 0; ch < 64; ch++) {
            sum += base[ch * 512] + base[ch * 512 + 128] +
                   base[ch * 512 + 256] + base[ch * 512 + 384];
        }
        red[tid] = (double)(logf(sum) - g_pos[row]);
        asm volatile("bar.sync 1, 256;" ::: "memory");
        for (int o = 128; o > 0; o >>= 1) {
            if (tid < o) red[tid] += red[tid + o];
            asm volatile("bar.sync 1, 256;" ::: "memory");
        }
        if (tid == 0) {
            g_bred[c] = red[0];
            __threadfence();
            unsigned int prev = atomicAdd(&g_cnt2, 1u);
            flag[0] = (prev == 31u) ? 1 : 0;
        }
        asm volatile("bar.sync 1, 256;" ::: "memory");
        if (flag[0] && tid < 32) {
            double v = g_bred[tid];
#pragma unroll
            for (int o = 16; o > 0; o >>= 1) v += __shfl_xor_sync(0xffffffffu, v, o);
            if (tid == 0) out[0] = (float)(v / (double)B_SZ);
        }
    }
}

// ---------------- launch ----------------
extern "C" void kernel_launch(void* const* d_in, const int* in_sizes, int n_in,
                              void* d_out, int out_size) {
    const float* h = (const float*)d_in[0];
    const float* r = (const float*)d_in[1];
    const float* t = (const float*)d_in[2];
    float* out = (float*)d_out;

    static int ncta = 0;
    if (ncta == 0) {
        cudaFuncSetAttribute(gemm_lse_kernel, cudaFuncAttributeMaxDynamicSharedMemorySize,
                             SMEM_TOTAL);
        int dev = 0, nsm = 148;
        cudaGetDevice(&dev);
        cudaDeviceGetAttribute(&nsm, cudaDevAttrMultiProcessorCount, dev);
        ncta = (nsm > 0) ? nsm : 148;
        if (ncta > NJOB) ncta = NJOB;
        if (ncta < 32) ncta = 32;
    }

    norm_kernel<<<B_SZ / 8, 256>>>(h, r, t);
    gemm_lse_kernel<<<ncta, NT, SMEM_TOTAL>>>(out);
}

// round 14
// speedup vs baseline: 1.0501x; 1.0501x over previous
#include <cuda_runtime.h>
#include <cuda_bf16.h>
#include <cstdint>
#include <math.h>

#define B_SZ 8192
#define D_SZ 256
#define INV_T (1.0f / 0.07f)
#define KC (1.4426950408889634f / 0.07f)   // log2(e)/T
#define NJOB 4096                           // 64 rowtiles x 64 chunks

// ---------------- scratch (no allocations allowed) ----------------
__device__ __align__(16) __nv_bfloat16 g_q[B_SZ * D_SZ];   // 4 MB
__device__ __align__(16) __nv_bfloat16 g_t[B_SZ * D_SZ];   // 4 MB
__device__ float g_pos[B_SZ];
__device__ float g_part[NJOB * 256];        // per job: 2 col-halves x 128 rows (4 MB)
__device__ double g_bred[32];
__device__ unsigned int g_cnt;              // jobs-done counter (gemm CTAs)
__device__ unsigned int g_cnt2;             // reduce-blocks counter

// ---------------- kernel 1: normalize (2 warps per row) ----------------
// 2048 blocks x 256 threads; 8 warps = 4 rows per block. Warp pair (2w, 2w+1)
// handles row; each warp covers 32 of the 64 float4 segments.
__global__ __launch_bounds__(256) void norm_kernel(const float* __restrict__ h,
                                                   const float* __restrict__ r,
                                                   const float* __restrict__ t) {
    if (blockIdx.x == 0 && threadIdx.x == 0) { g_cnt = 0; g_cnt2 = 0; }

    __shared__ float2 s_nrm[8];   // per-warp (ss, ts) partials
    __shared__ float s_pos[8];    // per-warp pos partials

    int wid = threadIdx.x >> 5;
    int lane = threadIdx.x & 31;
    int row = blockIdx.x * 4 + (wid >> 1);
    int half = wid & 1;
    int idx = half * 32 + lane;        // float4 index within the row [0,64)

    const float4* h4 = (const float4*)h;
    const float4* r4 = (const float4*)r;
    const float4* t4 = (const float4*)t;
    int base = row * 64;

    float4 ha = h4[base + idx];
    float4 ra = r4[base + idx];
    float4 ta = t4[base + idx];

    float4 va = make_float4(ha.x + ra.x, ha.y + ra.y, ha.z + ra.z, ha.w + ra.w);

    float ss = va.x * va.x + va.y * va.y + va.z * va.z + va.w * va.w;
    float ts = ta.x * ta.x + ta.y * ta.y + ta.z * ta.z + ta.w * ta.w;
#pragma unroll
    for (int o = 16; o > 0; o >>= 1) {
        ss += __shfl_xor_sync(0xffffffffu, ss, o);
        ts += __shfl_xor_sync(0xffffffffu, ts, o);
    }
    if (lane == 0) s_nrm[wid] = make_float2(ss, ts);
    __syncthreads();
    float2 other = s_nrm[wid ^ 1];
    float qinv = rsqrtf(fmaxf(ss + other.x, 1e-24f));
    float tinv = rsqrtf(fmaxf(ts + other.y, 1e-24f));

    float qa0 = va.x * qinv, qa1 = va.y * qinv, qa2 = va.z * qinv, qa3 = va.w * qinv;
    float ta0 = ta.x * tinv, ta1 = ta.y * tinv, ta2 = ta.z * tinv, ta3 = ta.w * tinv;

    __nv_bfloat162* q2 = (__nv_bfloat162*)(g_q + row * D_SZ);
    __nv_bfloat162* t2 = (__nv_bfloat162*)(g_t + row * D_SZ);
    int c2 = idx * 2;
    q2[c2]     = __floats2bfloat162_rn(qa0, qa1);
    q2[c2 + 1] = __floats2bfloat162_rn(qa2, qa3);
    t2[c2]     = __floats2bfloat162_rn(ta0, ta1);
    t2[c2 + 1] = __floats2bfloat162_rn(ta2, ta3);

    float p = qa0 * ta0 + qa1 * ta1 + qa2 * ta2 + qa3 * ta3;
#pragma unroll
    for (int o = 16; o > 0; o >>= 1) p += __shfl_xor_sync(0xffffffffu, p, o);
    if (lane == 0) s_pos[wid] = p;
    __syncthreads();
    if (half == 0 && lane == 0)
        g_pos[row] = (s_pos[wid] + s_pos[wid + 1]) * INV_T;
}

// ---------------- kernel 2: persistent HMMA GEMM + exp-sum + reduce tail ----------------
// (R12 config: 256 threads, warp tile 32x64, at the legacy-HMMA issue floor)
#define SQ 264                               // bf16 elems per smem row (+pad)
#define TBYTES (128 * SQ * 2)                // 67584 B per tile
#define QOFF 0
#define T0OFF TBYTES
#define T1OFF (2 * TBYTES)
#define SMEM_TOTAL (3 * TBYTES)

__device__ __forceinline__ void cp16(uint32_t dst, const void* src) {
    asm volatile("cp.async.cg.shared.global [%0], [%1], 16;\n" :: "r"(dst), "l"(src));
}
__device__ __forceinline__ void cp_commit() {
    asm volatile("cp.async.commit_group;\n" ::: "memory");
}
template <int N>
__device__ __forceinline__ void cp_wait() {
    asm volatile("cp.async.wait_group %0;\n" :: "n"(N) : "memory");
}

__device__ __forceinline__ void mma_bf16(float c[4], const uint32_t a[4], const uint32_t* b) {
    asm volatile(
        "mma.sync.aligned.m16n8k16.row.col.f32.bf16.bf16.f32 "
        "{%0,%1,%2,%3}, {%4,%5,%6,%7}, {%8,%9}, {%0,%1,%2,%3};\n"
        : "+f"(c[0]), "+f"(c[1]), "+f"(c[2]), "+f"(c[3])
        : "r"(a[0]), "r"(a[1]), "r"(a[2]), "r"(a[3]), "r"(b[0]), "r"(b[1]));
}

__global__ __launch_bounds__(256, 1) void gemm_lse_kernel(float* __restrict__ out) {
    extern __shared__ char smem[];
    const uint32_t sbase = (uint32_t)__cvta_generic_to_shared(smem);

    const int tid = threadIdx.x;
    const int wid = tid >> 5;
    const int lane = tid & 31;
    const int c = blockIdx.x;
    const int G = gridDim.x;

    const int j0 = (c * NJOB) / G;
    const int j1 = ((c + 1) * NJOB) / G;
    const int nj = j1 - j0;

    int cur_rt = j0 >> 6;

#define LOADQ(rt)                                                              \
    do {                                                                       \
        const __nv_bfloat16* qsrc = g_q + (size_t)((rt) * 128) * D_SZ;         \
        for (int i = tid; i < 128 * 32; i += 256) {                            \
            int rr = i >> 5;                                                   \
            int c8 = (i & 31) * 8;                                             \
            cp16(sbase + QOFF + (rr * SQ + c8) * 2, qsrc + rr * D_SZ + c8);    \
        }                                                                      \
    } while (0)
#define LOADT(off, ch)                                                         \
    do {                                                                       \
        const __nv_bfloat16* tsrc = g_t + (size_t)((ch) * 128) * D_SZ;         \
        for (int i = tid; i < 128 * 32; i += 256) {                            \
            int rr = i >> 5;                                                   \
            int c8 = (i & 31) * 8;                                             \
            cp16(sbase + (off) + (rr * SQ + c8) * 2, tsrc + rr * D_SZ + c8);   \
        }                                                                      \
    } while (0)

    // prologue: group0 = q + t[j0]; group1 = t[j0+1] (possibly empty)
    LOADQ(cur_rt);
    LOADT(T0OFF, j0 & 63);
    cp_commit();
    if (nj > 1) LOADT(T1OFF, (j0 + 1) & 63);
    cp_commit();

    // warp tile: 32 rows x 64 cols; warps 4 (rows) x 2 (cols)
    const int wr = (wid >> 1) * 32;
    const int wc = (wid & 1) * 64;

    uint32_t aAddr[2];
#pragma unroll
    for (int mt = 0; mt < 2; mt++) {
        int rrow = wr + mt * 16 + (lane & 15);
        aAddr[mt] = sbase + QOFF + (uint32_t)(rrow * SQ + (lane >> 4) * 8) * 2;
    }
    uint32_t bAddr[2][4];
#pragma unroll
    for (int p = 0; p < 4; p++) {
        int nt = 2 * p + (lane >> 4);
        int khalf = (lane >> 3) & 1;
        int rrow = wc + nt * 8 + (lane & 7);
        uint32_t off = (uint32_t)(rrow * SQ + khalf * 8) * 2;
        bAddr[0][p] = sbase + T0OFF + off;
        bAddr[1][p] = sbase + T1OFF + off;
    }

    for (int i = 0; i < nj; i++) {
        const int ji = j0 + i;
        const int rt = ji >> 6;
        const int cb = i & 1;

        if (rt != cur_rt) {
            LOADQ(rt);
            cp_commit();
            cp_wait<0>();
            cur_rt = rt;
        } else if (i >= nj - 2) {
            cp_wait<0>();
        } else {
            cp_wait<1>();
        }
        __syncthreads();

        float acc[2][8][4];
#pragma unroll
        for (int mt = 0; mt < 2; mt++)
#pragma unroll
            for (int nt = 0; nt < 8; nt++)
#pragma unroll
                for (int k = 0; k < 4; k++) acc[mt][nt][k] = 0.0f;

#pragma unroll
        for (int ks = 0; ks < 16; ks++) {
            uint32_t a[2][4];
            uint32_t b[8][2];
#pragma unroll
            for (int mt = 0; mt < 2; mt++) {
                asm volatile(
                    "ldmatrix.sync.aligned.m8n8.x4.shared.b16 {%0,%1,%2,%3}, [%4];\n"
                    : "=r"(a[mt][0]), "=r"(a[mt][1]), "=r"(a[mt][2]), "=r"(a[mt][3])
                    : "r"(aAddr[mt] + ks * 32));
            }
#pragma unroll
            for (int p = 0; p < 4; p++) {
                asm volatile(
                    "ldmatrix.sync.aligned.m8n8.x4.shared.b16 {%0,%1,%2,%3}, [%4];\n"
                    : "=r"(b[2 * p][0]), "=r"(b[2 * p][1]),
                      "=r"(b[2 * p + 1][0]), "=r"(b[2 * p + 1][1])
                    : "r"(bAddr[cb][p] + ks * 32));
            }
#pragma unroll
            for (int mt = 0; mt < 2; mt++)
#pragma unroll
                for (int nt = 0; nt < 8; nt++) mma_bf16(acc[mt][nt], a[mt], b[nt]);
        }

        // fused epilogue: exp2(acc*KC) -> per-thread row partials -> global
        float s[4];
#pragma unroll
        for (int mt = 0; mt < 2; mt++) {
            float s0 = 0.f, s1 = 0.f;
#pragma unroll
            for (int nt = 0; nt < 8; nt++) {
                s0 += exp2f(acc[mt][nt][0] * KC) + exp2f(acc[mt][nt][1] * KC);
                s1 += exp2f(acc[mt][nt][2] * KC) + exp2f(acc[mt][nt][3] * KC);
            }
            s[mt * 2] = s0;
            s[mt * 2 + 1] = s1;
        }
#pragma unroll
        for (int k = 0; k < 4; k++) {
            float v = s[k];
            v += __shfl_xor_sync(0xffffffffu, v, 1);
            v += __shfl_xor_sync(0xffffffffu, v, 2);
            s[k] = v;
        }
        if ((lane & 3) == 0) {
            int g = lane >> 2;
            float* dst = g_part + (size_t)ji * 256 + (wid & 1) * 128 + wr + g;
            dst[0] = s[0];
            dst[8] = s[1];
            dst[16] = s[2];
            dst[24] = s[3];
        }

        __syncthreads();
        if (i + 2 < nj) LOADT(cb ? T1OFF : T0OFF, (ji + 2) & 63);
        cp_commit();
    }
#undef LOADQ
#undef LOADT

    // ---------- tail: announce done; CTAs 0..31 wait for all, then reduce ----------
    __threadfence();
    __syncthreads();
    if (tid == 0) atomicAdd(&g_cnt, 1u);

    if (c < 32) {
        if (tid == 0) {
            while (*((volatile unsigned int*)&g_cnt) < (unsigned)G) { __nanosleep(64); }
        }
        __syncthreads();
        __threadfence();  // acquire: see all g_part writes

        double* red = (double*)smem;
        int* flag = (int*)(smem + 2048);
        int row = c * 256 + tid;
        int rt2 = row >> 7, rr2 = row & 127;
        const float* base = g_part + (size_t)(rt2 * 64) * 256 + rr2;
        float sum = 0.f;
#pragma unroll 8
        for (int ch = 0; ch < 64; ch++) sum += base[ch * 256] + base[ch * 256 + 128];
        red[tid] = (double)(logf(sum) - g_pos[row]);
        __syncthreads();
        for (int o = 128; o > 0; o >>= 1) {
            if (tid < o) red[tid] += red[tid + o];
            __syncthreads();
        }
        if (tid == 0) {
            g_bred[c] = red[0];
            __threadfence();
            unsigned int prev = atomicAdd(&g_cnt2, 1u);
            flag[0] = (prev == 31u) ? 1 : 0;
        }
        __syncthreads();
        if (flag[0] && tid < 32) {
            double v = g_bred[tid];
#pragma unroll
            for (int o = 16; o > 0; o >>= 1) v += __shfl_xor_sync(0xffffffffu, v, o);
            if (tid == 0) out[0] = (float)(v / (double)B_SZ);
        }
    }
}

// ---------------- launch ----------------
extern "C" void kernel_launch(void* const* d_in, const int* in_sizes, int n_in,
                              void* d_out, int out_size) {
    const float* h = (const float*)d_in[0];
    const float* r = (const float*)d_in[1];
    const float* t = (const float*)d_in[2];
    float* out = (float*)d_out;

    static int ncta = 0;
    if (ncta == 0) {
        cudaFuncSetAttribute(gemm_lse_kernel, cudaFuncAttributeMaxDynamicSharedMemorySize,
                             SMEM_TOTAL);
        int dev = 0, nsm = 148;
        cudaGetDevice(&dev);
        cudaDeviceGetAttribute(&nsm, cudaDevAttrMultiProcessorCount, dev);
        ncta = (nsm > 0) ? nsm : 148;
        if (ncta > NJOB) ncta = NJOB;
        if (ncta < 32) ncta = 32;
    }

    norm_kernel<<<B_SZ / 4, 256>>>(h, r, t);
    gemm_lse_kernel<<<ncta, 256, SMEM_TOTAL>>>(out);
}

// round 15
// speedup vs baseline: 1.0710x; 1.0200x over previous
#include <cuda_runtime.h>
#include <cuda_bf16.h>
#include <cstdint>
#include <math.h>

#define B_SZ 8192
#define D_SZ 256
#define INV_T (1.0f / 0.07f)
#define KC (1.4426950408889634f / 0.07f)   // log2(e)/T
#define NJOB 4096                           // 64 rowtiles x 64 chunks

// ---------------- scratch (no allocations allowed) ----------------
__device__ __align__(16) __nv_bfloat16 g_q[B_SZ * D_SZ];   // 4 MB
__device__ __align__(16) __nv_bfloat16 g_t[B_SZ * D_SZ];   // 4 MB
__device__ float g_pos[B_SZ];
__device__ float g_part[NJOB * 256];        // per job: 2 col-halves x 128 rows (4 MB)
__device__ double g_bred[32];
__device__ unsigned int g_cnt;              // jobs-done counter (gemm CTAs)
__device__ unsigned int g_cnt2;             // reduce-blocks counter

// ---------------- kernel 1: normalize (1 row/warp — best measured form) ----------------
__global__ __launch_bounds__(256) void norm_kernel(const float* __restrict__ h,
                                                   const float* __restrict__ r,
                                                   const float* __restrict__ t) {
    if (blockIdx.x == 0 && threadIdx.x == 0) { g_cnt = 0; g_cnt2 = 0; }

    int wid = threadIdx.x >> 5;
    int lane = threadIdx.x & 31;
    int row = blockIdx.x * 8 + wid;

    const float4* h4 = (const float4*)h;
    const float4* r4 = (const float4*)r;
    const float4* t4 = (const float4*)t;
    int base = row * 64;

    float4 ha = h4[base + lane];
    float4 hb = h4[base + 32 + lane];
    float4 ra = r4[base + lane];
    float4 rb = r4[base + 32 + lane];
    float4 ta = t4[base + lane];
    float4 tb = t4[base + 32 + lane];

    float4 va = make_float4(ha.x + ra.x, ha.y + ra.y, ha.z + ra.z, ha.w + ra.w);
    float4 vb = make_float4(hb.x + rb.x, hb.y + rb.y, hb.z + rb.z, hb.w + rb.w);

    float ss = va.x * va.x + va.y * va.y + va.z * va.z + va.w * va.w +
               vb.x * vb.x + vb.y * vb.y + vb.z * vb.z + vb.w * vb.w;
    float ts = ta.x * ta.x + ta.y * ta.y + ta.z * ta.z + ta.w * ta.w +
               tb.x * tb.x + tb.y * tb.y + tb.z * tb.z + tb.w * tb.w;
#pragma unroll
    for (int o = 16; o > 0; o >>= 1) {
        ss += __shfl_xor_sync(0xffffffffu, ss, o);
        ts += __shfl_xor_sync(0xffffffffu, ts, o);
    }
    float qinv = rsqrtf(fmaxf(ss, 1e-24f));
    float tinv = rsqrtf(fmaxf(ts, 1e-24f));

    float qa0 = va.x * qinv, qa1 = va.y * qinv, qa2 = va.z * qinv, qa3 = va.w * qinv;
    float qb0 = vb.x * qinv, qb1 = vb.y * qinv, qb2 = vb.z * qinv, qb3 = vb.w * qinv;
    float ta0 = ta.x * tinv, ta1 = ta.y * tinv, ta2 = ta.z * tinv, ta3 = ta.w * tinv;
    float tb0 = tb.x * tinv, tb1 = tb.y * tinv, tb2 = tb.z * tinv, tb3 = tb.w * tinv;

    __nv_bfloat162* q2 = (__nv_bfloat162*)(g_q + row * D_SZ);
    __nv_bfloat162* t2 = (__nv_bfloat162*)(g_t + row * D_SZ);
    int c2 = lane * 2;
    q2[c2]      = __floats2bfloat162_rn(qa0, qa1);
    q2[c2 + 1]  = __floats2bfloat162_rn(qa2, qa3);
    q2[c2 + 64] = __floats2bfloat162_rn(qb0, qb1);
    q2[c2 + 65] = __floats2bfloat162_rn(qb2, qb3);
    t2[c2]      = __floats2bfloat162_rn(ta0, ta1);
    t2[c2 + 1]  = __floats2bfloat162_rn(ta2, ta3);
    t2[c2 + 64] = __floats2bfloat162_rn(tb0, tb1);
    t2[c2 + 65] = __floats2bfloat162_rn(tb2, tb3);

    float p = qa0 * ta0 + qa1 * ta1 + qa2 * ta2 + qa3 * ta3 +
              qb0 * tb0 + qb1 * tb1 + qb2 * tb2 + qb3 * tb3;
#pragma unroll
    for (int o = 16; o > 0; o >>= 1) p += __shfl_xor_sync(0xffffffffu, p, o);
    if (lane == 0) g_pos[row] = p * INV_T;
}

// ---------------- kernel 2: persistent HMMA GEMM + exp-sum + reduce tail ----------------
// 256 threads, warp tile 32x64 — at the sm_103a legacy-HMMA rate limit.
#define SQ 264                               // bf16 elems per smem row (+pad)
#define TBYTES (128 * SQ * 2)                // 67584 B per tile
#define QOFF 0
#define T0OFF TBYTES
#define T1OFF (2 * TBYTES)
#define SMEM_TOTAL (3 * TBYTES)

__device__ __forceinline__ void cp16(uint32_t dst, const void* src) {
    asm volatile("cp.async.cg.shared.global [%0], [%1], 16;\n" :: "r"(dst), "l"(src));
}
__device__ __forceinline__ void cp_commit() {
    asm volatile("cp.async.commit_group;\n" ::: "memory");
}
template <int N>
__device__ __forceinline__ void cp_wait() {
    asm volatile("cp.async.wait_group %0;\n" :: "n"(N) : "memory");
}

__device__ __forceinline__ void mma_bf16(float c[4], const uint32_t a[4], const uint32_t* b) {
    asm volatile(
        "mma.sync.aligned.m16n8k16.row.col.f32.bf16.bf16.f32 "
        "{%0,%1,%2,%3}, {%4,%5,%6,%7}, {%8,%9}, {%0,%1,%2,%3};\n"
        : "+f"(c[0]), "+f"(c[1]), "+f"(c[2]), "+f"(c[3])
        : "r"(a[0]), "r"(a[1]), "r"(a[2]), "r"(a[3]), "r"(b[0]), "r"(b[1]));
}

__global__ __launch_bounds__(256, 1) void gemm_lse_kernel(float* __restrict__ out) {
    extern __shared__ char smem[];
    const uint32_t sbase = (uint32_t)__cvta_generic_to_shared(smem);

    const int tid = threadIdx.x;
    const int wid = tid >> 5;
    const int lane = tid & 31;
    const int c = blockIdx.x;
    const int G = gridDim.x;

    const int j0 = (c * NJOB) / G;
    const int j1 = ((c + 1) * NJOB) / G;
    const int nj = j1 - j0;

    int cur_rt = j0 >> 6;

#define LOADQ(rt)                                                              \
    do {                                                                       \
        const __nv_bfloat16* qsrc = g_q + (size_t)((rt) * 128) * D_SZ;         \
        for (int i = tid; i < 128 * 32; i += 256) {                            \
            int rr = i >> 5;                                                   \
            int c8 = (i & 31) * 8;                                             \
            cp16(sbase + QOFF + (rr * SQ + c8) * 2, qsrc + rr * D_SZ + c8);    \
        }                                                                      \
    } while (0)
#define LOADT(off, ch)                                                         \
    do {                                                                       \
        const __nv_bfloat16* tsrc = g_t + (size_t)((ch) * 128) * D_SZ;         \
        for (int i = tid; i < 128 * 32; i += 256) {                            \
            int rr = i >> 5;                                                   \
            int c8 = (i & 31) * 8;                                             \
            cp16(sbase + (off) + (rr * SQ + c8) * 2, tsrc + rr * D_SZ + c8);   \
        }                                                                      \
    } while (0)

    // prologue: group0 = q + t[j0]; group1 = t[j0+1] (possibly empty)
    LOADQ(cur_rt);
    LOADT(T0OFF, j0 & 63);
    cp_commit();
    if (nj > 1) LOADT(T1OFF, (j0 + 1) & 63);
    cp_commit();

    // warp tile: 32 rows x 64 cols; warps 4 (rows) x 2 (cols)
    const int wr = (wid >> 1) * 32;
    const int wc = (wid & 1) * 64;

    uint32_t aAddr[2];
#pragma unroll
    for (int mt = 0; mt < 2; mt++) {
        int rrow = wr + mt * 16 + (lane & 15);
        aAddr[mt] = sbase + QOFF + (uint32_t)(rrow * SQ + (lane >> 4) * 8) * 2;
    }
    uint32_t bAddr[2][4];
#pragma unroll
    for (int p = 0; p < 4; p++) {
        int nt = 2 * p + (lane >> 4);
        int khalf = (lane >> 3) & 1;
        int rrow = wc + nt * 8 + (lane & 7);
        uint32_t off = (uint32_t)(rrow * SQ + khalf * 8) * 2;
        bAddr[0][p] = sbase + T0OFF + off;
        bAddr[1][p] = sbase + T1OFF + off;
    }

    for (int i = 0; i < nj; i++) {
        const int ji = j0 + i;
        const int rt = ji >> 6;
        const int cb = i & 1;

        if (rt != cur_rt) {
            LOADQ(rt);
            cp_commit();
            cp_wait<0>();
            cur_rt = rt;
        } else if (i >= nj - 2) {
            cp_wait<0>();
        } else {
            cp_wait<1>();
        }
        __syncthreads();

        float acc[2][8][4];
#pragma unroll
        for (int mt = 0; mt < 2; mt++)
#pragma unroll
            for (int nt = 0; nt < 8; nt++)
#pragma unroll
                for (int k = 0; k < 4; k++) acc[mt][nt][k] = 0.0f;

#pragma unroll
        for (int ks = 0; ks < 16; ks++) {
            uint32_t a[2][4];
            uint32_t b[8][2];
#pragma unroll
            for (int mt = 0; mt < 2; mt++) {
                asm volatile(
                    "ldmatrix.sync.aligned.m8n8.x4.shared.b16 {%0,%1,%2,%3}, [%4];\n"
                    : "=r"(a[mt][0]), "=r"(a[mt][1]), "=r"(a[mt][2]), "=r"(a[mt][3])
                    : "r"(aAddr[mt] + ks * 32));
            }
#pragma unroll
            for (int p = 0; p < 4; p++) {
                asm volatile(
                    "ldmatrix.sync.aligned.m8n8.x4.shared.b16 {%0,%1,%2,%3}, [%4];\n"
                    : "=r"(b[2 * p][0]), "=r"(b[2 * p][1]),
                      "=r"(b[2 * p + 1][0]), "=r"(b[2 * p + 1][1])
                    : "r"(bAddr[cb][p] + ks * 32));
            }
#pragma unroll
            for (int mt = 0; mt < 2; mt++)
#pragma unroll
                for (int nt = 0; nt < 8; nt++) mma_bf16(acc[mt][nt], a[mt], b[nt]);
        }

        // fused epilogue: exp2(acc*KC) -> per-thread row partials -> global
        float s[4];
#pragma unroll
        for (int mt = 0; mt < 2; mt++) {
            float s0 = 0.f, s1 = 0.f;
#pragma unroll
            for (int nt = 0; nt < 8; nt++) {
                s0 += exp2f(acc[mt][nt][0] * KC) + exp2f(acc[mt][nt][1] * KC);
                s1 += exp2f(acc[mt][nt][2] * KC) + exp2f(acc[mt][nt][3] * KC);
            }
            s[mt * 2] = s0;
            s[mt * 2 + 1] = s1;
        }
#pragma unroll
        for (int k = 0; k < 4; k++) {
            float v = s[k];
            v += __shfl_xor_sync(0xffffffffu, v, 1);
            v += __shfl_xor_sync(0xffffffffu, v, 2);
            s[k] = v;
        }
        if ((lane & 3) == 0) {
            int g = lane >> 2;
            float* dst = g_part + (size_t)ji * 256 + (wid & 1) * 128 + wr + g;
            dst[0] = s[0];
            dst[8] = s[1];
            dst[16] = s[2];
            dst[24] = s[3];
        }

        __syncthreads();
        if (i + 2 < nj) LOADT(cb ? T1OFF : T0OFF, (ji + 2) & 63);
        cp_commit();
    }
#undef LOADQ
#undef LOADT

    // ---------- tail: announce done; CTAs 0..31 wait for all, then reduce ----------
    __threadfence();
    __syncthreads();
    if (tid == 0) atomicAdd(&g_cnt, 1u);

    if (c < 32) {
        if (tid == 0) {
            while (*((volatile unsigned int*)&g_cnt) < (unsigned)G) { __nanosleep(64); }
        }
        __syncthreads();
        __threadfence();  // acquire: see all g_part writes

        double* red = (double*)smem;
        int* flag = (int*)(smem + 2048);
        int row = c * 256 + tid;
        int rt2 = row >> 7, rr2 = row & 127;
        const float* base = g_part + (size_t)(rt2 * 64) * 256 + rr2;
        float sum = 0.f;
#pragma unroll 8
        for (int ch = 0; ch < 64; ch++) sum += base[ch * 256] + base[ch * 256 + 128];
        red[tid] = (double)(logf(sum) - g_pos[row]);
        __syncthreads();
        for (int o = 128; o > 0; o >>= 1) {
            if (tid < o) red[tid] += red[tid + o];
            __syncthreads();
        }
        if (tid == 0) {
            g_bred[c] = red[0];
            __threadfence();
            unsigned int prev = atomicAdd(&g_cnt2, 1u);
            flag[0] = (prev == 31u) ? 1 : 0;
        }
        __syncthreads();
        if (flag[0] && tid < 32) {
            double v = g_bred[tid];
#pragma unroll
            for (int o = 16; o > 0; o >>= 1) v += __shfl_xor_sync(0xffffffffu, v, o);
            if (tid == 0) out[0] = (float)(v / (double)B_SZ);
        }
    }
}

// ---------------- launch ----------------
extern "C" void kernel_launch(void* const* d_in, const int* in_sizes, int n_in,
                              void* d_out, int out_size) {
    const float* h = (const float*)d_in[0];
    const float* r = (const float*)d_in[1];
    const float* t = (const float*)d_in[2];
    float* out = (float*)d_out;

    static int ncta = 0;
    if (ncta == 0) {
        cudaFuncSetAttribute(gemm_lse_kernel, cudaFuncAttributeMaxDynamicSharedMemorySize,
                             SMEM_TOTAL);
        int dev = 0, nsm = 148;
        cudaGetDevice(&dev);
        cudaDeviceGetAttribute(&nsm, cudaDevAttrMultiProcessorCount, dev);
        ncta = (nsm > 0) ? nsm : 148;
        if (ncta > NJOB) ncta = NJOB;
        if (ncta < 32) ncta = 32;
    }

    norm_kernel<<<B_SZ / 8, 256>>>(h, r, t);
    gemm_lse_kernel<<<ncta, 256, SMEM_TOTAL>>>(out);
}